// round 1
// baseline (speedup 1.0000x reference)
#include <cuda_runtime.h>

// GraphAttention collapsed form:
//   v[b,n] = x[b, NEF + n]
//   c1 = sum_f W[f]*a[f], c2 = sum_f W[f]*a[64+f]
//   e(i,o) = c1*v[i] + c2*v[(i+o)%N],  o in [0,17)
//   denom[b] = sum over all N*17 edges of exp(lrelu(e))
//   s[b,i]   = (1/denom) * sum_o exp(lrelu(e(i,o))) * v[(i+o)%N]
//   out[b,i,f] = lrelu(W[f] * s[b,i])

#define NB      8
#define NN      4096
#define NOFF    17      // DEG+1
#define FOUT    64
#define NEF     4096
#define CHUNKS  16
#define CNODES  256     // nodes per block in kA  (CHUNKS*CNODES == NN)
#define BNODES  64      // nodes per block in kB

__device__ float g_partials[NB * CHUNKS];

__device__ __forceinline__ float lrelu(float x) { return x > 0.0f ? x : 0.01f * x; }

// Compute c1 = W.a[:64], c2 = W.a[64:] into sc[0..1]. Deterministic serial sum.
__device__ __forceinline__ void compute_c(const float* __restrict__ W,
                                          const float* __restrict__ a,
                                          float* sc, float* sred) {
    int t = threadIdx.x;
    if (t < 64)       sred[t] = W[t] * a[t];
    else if (t < 128) sred[t] = W[t - 64] * a[t];   // a[64 + (t-64)]
    __syncthreads();
    if (t == 0) {
        float s1 = 0.0f, s2 = 0.0f;
#pragma unroll
        for (int f = 0; f < 64; f++) { s1 += sred[f]; s2 += sred[64 + f]; }
        sc[0] = s1; sc[1] = s2;
    }
    __syncthreads();
}

// Kernel A: per-(batch,chunk) partial softmax denominator.
__global__ void __launch_bounds__(256) ga_reduce(const float* __restrict__ x,
                                                 const float* __restrict__ W,
                                                 const float* __restrict__ a) {
    __shared__ float sv[CNODES + 16];
    __shared__ float sred[256];
    __shared__ float sc[2];

    int b     = blockIdx.x / CHUNKS;
    int chunk = blockIdx.x % CHUNKS;
    int base  = chunk * CNODES;
    const float* v = x + (size_t)b * (NEF + NN) + NEF;
    int t = threadIdx.x;

    compute_c(W, a, sc, sred);

    for (int i = t; i < CNODES + 16; i += 256)
        sv[i] = v[(base + i) & (NN - 1)];
    __syncthreads();

    float c1 = sc[0], c2 = sc[1];
    float vi = sv[t];
    float sum = 0.0f;
#pragma unroll
    for (int o = 0; o < NOFF; o++) {
        float e = fmaf(c1, vi, c2 * sv[t + o]);
        sum += __expf(lrelu(e));
    }
    __syncthreads();              // sred reuse: c-phase fully consumed
    sred[t] = sum;
    __syncthreads();
#pragma unroll
    for (int s = 128; s > 0; s >>= 1) {
        if (t < s) sred[t] += sred[t + s];
        __syncthreads();
    }
    if (t == 0) g_partials[b * CHUNKS + chunk] = sred[0];
}

// Kernel B: per-node weighted sum + output store (64 nodes x 64 feat per block).
__global__ void __launch_bounds__(256) ga_out(const float* __restrict__ x,
                                              const float* __restrict__ Wg,
                                              const float* __restrict__ a,
                                              float* __restrict__ out) {
    __shared__ float sv[BNODES + 16];
    __shared__ float ss[BNODES];
    __shared__ float sW[FOUT];
    __shared__ float sred[256];
    __shared__ float sc[2];
    __shared__ float sinv;

    int b    = blockIdx.x / (NN / BNODES);
    int nb   = blockIdx.x % (NN / BNODES);
    int base = nb * BNODES;
    const float* v = x + (size_t)b * (NEF + NN) + NEF;
    int t = threadIdx.x;

    compute_c(Wg, a, sc, sred);

    if (t < FOUT) sW[t] = Wg[t];
    for (int i = t; i < BNODES + 16; i += 256)
        sv[i] = v[(base + i) & (NN - 1)];
    if (t == 0) {
        float d = 0.0f;
#pragma unroll
        for (int k = 0; k < CHUNKS; k++) d += g_partials[b * CHUNKS + k];
        sinv = 1.0f / d;
    }
    __syncthreads();

    float c1 = sc[0], c2 = sc[1], inv = sinv;
    if (t < BNODES) {
        float vi = sv[t];
        float s = 0.0f;
#pragma unroll
        for (int o = 0; o < NOFF; o++) {
            float vj = sv[t + o];
            s += __expf(lrelu(fmaf(c1, vi, c2 * vj))) * vj;
        }
        ss[t] = s * inv;
    }
    __syncthreads();

    // 64 nodes x 64 floats = 1024 float4, fully coalesced.
    float4* o4 = (float4*)(out + ((size_t)b * NN + base) * FOUT);
    const float4* w4 = (const float4*)sW;
#pragma unroll
    for (int k = 0; k < 4; k++) {
        int idx  = t + k * 256;   // 0..1023
        int node = idx >> 4;      // /16 float4 per node
        int f4   = idx & 15;
        float s  = ss[node];
        float4 w = w4[f4];
        float4 r;
        r.x = lrelu(s * w.x);
        r.y = lrelu(s * w.y);
        r.z = lrelu(s * w.z);
        r.w = lrelu(s * w.w);
        o4[idx] = r;
    }
}

extern "C" void kernel_launch(void* const* d_in, const int* in_sizes, int n_in,
                              void* d_out, int out_size) {
    const float* x = (const float*)d_in[0];
    const float* W = (const float*)d_in[1];
    const float* a = (const float*)d_in[2];
    float* out = (float*)d_out;

    ga_reduce<<<NB * CHUNKS, 256>>>(x, W, a);
    ga_out<<<NB * (NN / BNODES), 256>>>(x, W, a, out);
}

// round 2
// speedup vs baseline: 1.0060x; 1.0060x over previous
#include <cuda_runtime.h>

// GraphAttention collapsed form (validated R1, rel_err 1.7e-7):
//   v[b,n] = x[b, NEF + n]
//   c1 = W.a[:64], c2 = W.a[64:]   (scalars)
//   w(i,o) = exp(lrelu(c1*v[i] + c2*v[(i+o)%N])),  o in [0,17)
//   denom[b] = sum_{i,o} w(i,o)
//   s[b,i]   = sum_o w(i,o)*v[(i+o)%N]
//   out[b,i,f] = lrelu(W[f] * s[b,i] / denom[b])    (lrelu pos-homogeneous)
//
// Single fused kernel: phase1 (s + partial denom) -> grid barrier -> phase2
// (denom sum + coalesced float4 output from smem-resident s).

#define NB      8
#define NN      4096
#define NOFF    17
#define FOUT    64
#define NEF     4096
#define BPB     32            // blocks per batch
#define BNODES  128           // nodes per block (BPB*BNODES == NN)
#define GRID    (NB * BPB)    // 256 blocks — < 148 SMs * 2 resident => wave-1 co-resident

__device__ float        g_part[GRID];
__device__ unsigned int g_ctr   = 0;
__device__ unsigned int g_sense = 0;

__device__ __forceinline__ float lrelu(float x) { return x > 0.0f ? x : 0.01f * x; }

__global__ void __launch_bounds__(256, 2)
ga_fused(const float* __restrict__ x,
         const float* __restrict__ W,
         const float* __restrict__ a,
         float* __restrict__ out) {
    __shared__ float sv[BNODES + 16];
    __shared__ float ssn[BNODES];
    __shared__ float sW[FOUT];
    __shared__ float sred[256];
    __shared__ float sc[2];
    __shared__ float sinv;

    const int b     = blockIdx.x >> 5;      // /BPB
    const int chunk = blockIdx.x & (BPB - 1);
    const int base  = chunk * BNODES;
    const float* v  = x + (size_t)b * (NEF + NN) + NEF;
    const int t = threadIdx.x;

    // parallel loads: node values, W, and c-products (disjoint thread ranges ok)
    if (t < BNODES + 16) sv[t] = v[(base + t) & (NN - 1)];
    if (t >= 192)        sW[t - 192] = W[t - 192];
    if (t < 128)         sred[t] = W[t & 63] * a[t];
    __syncthreads();
    if (t == 0) {
        float s1 = 0.0f, s2 = 0.0f;
#pragma unroll
        for (int f = 0; f < 64; f++) { s1 += sred[f]; s2 += sred[64 + f]; }
        sc[0] = s1; sc[1] = s2;
    }
    __syncthreads();

    const float c1 = sc[0], c2 = sc[1];
    float esum = 0.0f;
    if (t < BNODES) {
        const float vi = sv[t];
        float s = 0.0f;
#pragma unroll
        for (int o = 0; o < NOFF; o++) {
            const float vj = sv[t + o];
            const float w  = __expf(lrelu(fmaf(c1, vi, c2 * vj)));
            esum += w;
            s    += w * vj;
        }
        ssn[t] = s;
    }
    __syncthreads();                       // sred c-products fully consumed
    sred[t] = esum;
    __syncthreads();
#pragma unroll
    for (int s = 128; s > 0; s >>= 1) {
        if (t < s) sred[t] += sred[t + s];
        __syncthreads();
    }
    if (t == 0) g_part[blockIdx.x] = sred[0];

    // ---- grid barrier (sense-reversing, self-resetting across graph replays)
    if (t == 0) {
        __threadfence();                               // flush g_part
        const unsigned my_sense = atomicAdd(&g_sense, 0u);
        const unsigned old      = atomicAdd(&g_ctr, 1u);
        if (old == GRID - 1) {
            g_ctr = 0;                                 // reset for next replay
            __threadfence();
            atomicAdd(&g_sense, 1u);                   // release
        } else {
            while (atomicAdd(&g_sense, 0u) == my_sense) __nanosleep(64);
        }
    }
    __syncthreads();

    // ---- denom for this batch (deterministic fixed-order serial sum)
    if (t == 0) {
        float d = 0.0f;
#pragma unroll
        for (int k = 0; k < BPB; k++) d += __ldcg(&g_part[b * BPB + k]);
        sinv = 1.0f / d;
    }
    __syncthreads();
    if (t < BNODES) ssn[t] *= sinv;
    __syncthreads();

    // ---- output: 128 nodes x 64 feats = 2048 float4, fully coalesced
    float4* o4 = (float4*)(out + ((size_t)b * NN + base) * FOUT);
    const float4* w4 = (const float4*)sW;
#pragma unroll
    for (int k = 0; k < 8; k++) {
        const int idx  = t + k * 256;   // 0..2047
        const int node = idx >> 4;
        const int f4   = idx & 15;
        const float s  = ssn[node];
        const float4 w = w4[f4];
        float4 r;
        r.x = lrelu(s * w.x);
        r.y = lrelu(s * w.y);
        r.z = lrelu(s * w.z);
        r.w = lrelu(s * w.w);
        o4[idx] = r;
    }
}

extern "C" void kernel_launch(void* const* d_in, const int* in_sizes, int n_in,
                              void* d_out, int out_size) {
    const float* x = (const float*)d_in[0];
    const float* W = (const float*)d_in[1];
    const float* a = (const float*)d_in[2];
    float* out = (float*)d_out;

    ga_fused<<<GRID, 256>>>(x, W, a, out);
}